// round 15
// baseline (speedup 1.0000x reference)
#include <cuda_runtime.h>
#include <cuda_fp16.h>
#include <cstdint>

// Problem constants
#define BB 4
#define TTOT 4096
#define CC 1024
#define HH 16
#define KK 64
#define TCH 128
#define NCH 32            // TTOT / TCH
#define MM (BB * TTOT)    // 16384 rows
#define ELEMS (MM * CC)   // 16,777,216
#define WEL (CC * CC)

// ---------------- scratch (device globals; no allocation allowed) ----------
__device__ __half g_ah[4][ELEMS];   // mixes: r,k,v,g (fp16)
__device__ __half g_wh[5][WEL];     // weights fp16: r,k,v,g,o
__device__ float g_r[ELEMS];
__device__ float g_k[ELEMS];
__device__ float g_v[ELEMS];
__device__ float g_g[ELEMS];
__device__ float g_states[NCH * BB * HH * KK * KK];
__device__ float g_xo[ELEMS];
__device__ __half g_gh[ELEMS];      // gated output (fp16)

// ==================== mma.sync fp16 GEMM (1- or 2-product) ==================
// C = (Ah [+ Al]) @ Wh^T ; per-problem useAl flag (all 0 in this round).
// CTA 128x128, BK=32, 2-stage cp.async, 4 warps (2m x 2n), warp 64x64.
#define G2_PITCH 80
#define G2_TILE 10240                 // 128 rows * 80 B
#define G2_STAGE 30720                // Ah, Al, Bh
#define G2_SMEM 61440                 // 2 stages

struct GArgs {
    const __half* Ah[4];
    const __half* Al[4];
    const __half* Bh[4];
    float* C[4];
    int useAl[4];
};

#define CP16(dst, src) \
    asm volatile("cp.async.cg.shared.global [%0], [%1], 16;" :: "r"(dst), "l"(src) : "memory")

#define LDSM4(r0, r1, r2, r3, a) \
    asm volatile("ldmatrix.sync.aligned.m8n8.x4.shared.b16 {%0,%1,%2,%3}, [%4];" \
                 : "=r"(r0), "=r"(r1), "=r"(r2), "=r"(r3) : "r"(a))

#define MMA16816(d, a, b0, b1) \
    asm volatile("mma.sync.aligned.m16n8k16.row.col.f32.f16.f16.f32 " \
                 "{%0,%1,%2,%3},{%4,%5,%6,%7},{%8,%9},{%0,%1,%2,%3};" \
                 : "+f"((d)[0]), "+f"((d)[1]), "+f"((d)[2]), "+f"((d)[3]) \
                 : "r"((a)[0]), "r"((a)[1]), "r"((a)[2]), "r"((a)[3]), "r"(b0), "r"(b1))

__global__ __launch_bounds__(128, 2) void gemm_fp16(GArgs ga) {
    extern __shared__ __align__(128) char smraw[];
    const uint32_t smb = (uint32_t)__cvta_generic_to_shared(smraw);
    const int prob = blockIdx.z;
    const __half* __restrict__ Ahi = ga.Ah[prob];
    const __half* __restrict__ Alo = ga.Al[prob];
    const __half* __restrict__ Bhi = ga.Bh[prob];
    float* __restrict__ C = ga.C[prob];
    const bool useAl = ga.useAl[prob] != 0;

    const int tid = threadIdx.x;
    const int lane = tid & 31;
    const int wid = tid >> 5;
    const int warp_m = wid & 1;
    const int warp_n = wid >> 1;
    const int m0 = blockIdx.y * 128;
    const int n0 = blockIdx.x * 128;

    const int lrow = tid >> 2;        // 0..31
    const int lseg = tid & 3;
    const long arow0 = (long)(m0 + lrow) * CC + lseg * 8;
    const long brow0 = (long)(n0 + lrow) * CC + lseg * 8;
    const uint32_t dof0 = lrow * G2_PITCH + lseg * 16;

#define G2_LOAD(s, ch) do {                                                  \
        uint32_t st_ = smb + (s) * G2_STAGE;                                 \
        long kb_ = (long)(ch) * 32;                                          \
        _Pragma("unroll")                                                    \
        for (int i_ = 0; i_ < 4; i_++) {                                     \
            long ro_ = (long)i_ * 32 * CC + kb_;                             \
            uint32_t do_ = dof0 + i_ * 32 * G2_PITCH;                        \
            CP16(st_ + do_,               Ahi + arow0 + ro_);                \
            if (useAl) CP16(st_ + G2_TILE + do_, Alo + arow0 + ro_);         \
            CP16(st_ + 2 * G2_TILE + do_, Bhi + brow0 + ro_);                \
        }                                                                    \
        asm volatile("cp.async.commit_group;" ::: "memory");                 \
    } while (0)

    float acc[4][8][4];
#pragma unroll
    for (int mt = 0; mt < 4; mt++)
#pragma unroll
        for (int j = 0; j < 8; j++)
#pragma unroll
            for (int q = 0; q < 4; q++) acc[mt][j][q] = 0.0f;

    const int g = lane >> 3;
    const uint32_t aoff = (uint32_t)((warp_m * 64 + ((g & 1) << 3) + (lane & 7)) * G2_PITCH
                                     + ((g >> 1) << 4));
    const uint32_t boff = (uint32_t)((warp_n * 64 + ((g >> 1) << 3) + (lane & 7)) * G2_PITCH
                                     + ((g & 1) << 4));

    G2_LOAD(0, 0);

    for (int c = 0; c < 32; ++c) {
        if (c + 1 < 32) G2_LOAD((c + 1) & 1, c + 1);
        if (c + 1 < 32)
            asm volatile("cp.async.wait_group 1;" ::: "memory");
        else
            asm volatile("cp.async.wait_group 0;" ::: "memory");
        __syncthreads();

        uint32_t st = smb + (c & 1) * G2_STAGE;
#pragma unroll
        for (int ks = 0; ks < 2; ks++) {
            uint32_t ko = ks * 32;
            uint32_t ah_[4][4];
#pragma unroll
            for (int mt = 0; mt < 4; mt++)
                LDSM4(ah_[mt][0], ah_[mt][1], ah_[mt][2], ah_[mt][3],
                      st + aoff + mt * (16 * G2_PITCH) + ko);
            uint32_t bh_[8][2];
#pragma unroll
            for (int t = 0; t < 4; t++)
                LDSM4(bh_[2 * t][0], bh_[2 * t][1], bh_[2 * t + 1][0], bh_[2 * t + 1][1],
                      st + 2 * G2_TILE + boff + t * (16 * G2_PITCH) + ko);
            // P1: Ah x Bh
#pragma unroll
            for (int mt = 0; mt < 4; mt++)
#pragma unroll
                for (int j = 0; j < 8; j++)
                    MMA16816(acc[mt][j], ah_[mt], bh_[j][0], bh_[j][1]);
            // P2: Al x Bh (disabled this round)
            if (useAl) {
                uint32_t al_[4][4];
#pragma unroll
                for (int mt = 0; mt < 4; mt++)
                    LDSM4(al_[mt][0], al_[mt][1], al_[mt][2], al_[mt][3],
                          st + G2_TILE + aoff + mt * (16 * G2_PITCH) + ko);
#pragma unroll
                for (int mt = 0; mt < 4; mt++)
#pragma unroll
                    for (int j = 0; j < 8; j++)
                        MMA16816(acc[mt][j], al_[mt], bh_[j][0], bh_[j][1]);
            }
        }
        __syncthreads();
    }

    const int erow = m0 + warp_m * 64 + (lane >> 2);
    const int ecol = n0 + warp_n * 64 + (lane & 3) * 2;
#pragma unroll
    for (int mt = 0; mt < 4; mt++) {
#pragma unroll
        for (int j = 0; j < 8; j++) {
            long r = erow + mt * 16;
            int cc2 = ecol + j * 8;
            *(float2*)(C + r * CC + cc2) = make_float2(acc[mt][j][0], acc[mt][j][1]);
            *(float2*)(C + (r + 8) * CC + cc2) = make_float2(acc[mt][j][2], acc[mt][j][3]);
        }
    }
}

// ---------------- weight fp32 -> fp16 (all 5, vectorized) -------------------
struct WArgs { const float* w[5]; };

__global__ __launch_bounds__(256) void conv_w5(WArgs wa) {
    const int wi = blockIdx.y;
    const float* __restrict__ src = wa.w[wi];
    long e0 = ((long)blockIdx.x * 256 + threadIdx.x) * 4;
    float4 x4 = *(const float4*)(src + e0);
    __half2* hp = (__half2*)&g_wh[wi][e0];
    hp[0] = __floats2half2_rn(x4.x, x4.y);
    hp[1] = __floats2half2_rn(x4.z, x4.w);
}

// ---------------- kernel 1: token shift + 4 mixes -> fp16 -------------------
__global__ __launch_bounds__(256) void mix_kernel(const float* __restrict__ x,
                                                  const float* __restrict__ tmr,
                                                  const float* __restrict__ tmk,
                                                  const float* __restrict__ tmv,
                                                  const float* __restrict__ tmg) {
    long e0 = ((long)blockIdx.x * 256 + threadIdx.x) * 4;
    if (e0 >= (long)ELEMS) return;
    int c = (int)(e0 % CC);
    long row = e0 / CC;
    int t = (int)(row % TTOT);
    float4 xv = *(const float4*)(x + e0);
    float4 xx = (t > 0) ? *(const float4*)(x + e0 - CC) : make_float4(0.f, 0.f, 0.f, 0.f);
    const float* tms[4] = {tmr, tmk, tmv, tmg};
#pragma unroll
    for (int mi = 0; mi < 4; mi++) {
        float4 m = *(const float4*)(tms[mi] + c);
        float y0 = xv.x * m.x + xx.x * (1.0f - m.x);
        float y1 = xv.y * m.y + xx.y * (1.0f - m.y);
        float y2 = xv.z * m.z + xx.z * (1.0f - m.z);
        float y3 = xv.w * m.w + xx.w * (1.0f - m.w);
        __half2* hp = (__half2*)&g_ah[mi][e0];
        hp[0] = __floats2half2_rn(y0, y1);
        hp[1] = __floats2half2_rn(y2, y3);
    }
}

// ---------------- kernel 3: state sweep, half-chunk staging (40 KB smem) ----
#define WS_SMEM 40960
__global__ __launch_bounds__(256) void wkv_states(const float* __restrict__ time_decay) {
    extern __shared__ __align__(16) float sms[];
    const uint32_t smb = (uint32_t)__cvta_generic_to_shared(sms);
    __shared__ float wk_s[TCH];

    int bx = blockIdx.x;             // 0..255
    int bh = bx >> 2, kq = bx & 3;
    int b = bh / HH, h = bh % HH;
    int tid = threadIdx.x;
    int vd = tid & 63, sub = tid >> 6;
    float et = expf(time_decay[h]);
    float ws = expf(-et * (float)TCH);

    const float* kg = g_k + ((long)b * TTOT) * CC + h * KK + kq * 16;
    const float* vg = g_v + ((long)b * TTOT) * CC + h * KK;

#define WS_LOAD(buf, hh) do {                                                    \
        uint32_t kdst = smb + (buf) * 4096;                                      \
        uint32_t vdst = smb + 8192 + (buf) * 16384;                              \
        {                                                                        \
            int row_ = tid >> 2, c4_ = tid & 3;                                  \
            CP16(kdst + row_ * 64 + c4_ * 16,                                    \
                 kg + (long)((hh) * 64 + row_) * CC + c4_ * 4);                  \
        }                                                                        \
        _Pragma("unroll")                                                        \
        for (int it_ = 0; it_ < 4; it_++) {                                      \
            int f_ = it_ * 256 + tid, row_ = f_ >> 4, c4_ = f_ & 15;             \
            CP16(vdst + row_ * 256 + c4_ * 16,                                   \
                 vg + (long)((hh) * 64 + row_) * CC + c4_ * 4);                  \
        }                                                                        \
        asm volatile("cp.async.commit_group;" ::: "memory");                     \
    } while (0)

    WS_LOAD(0, 0);
    if (tid < TCH) wk_s[tid] = expf(-et * (float)(TCH - 1 - tid));

    float s[4] = {0.f, 0.f, 0.f, 0.f};

    for (int hh = 0; hh < 2 * NCH; hh++) {
        if (!(hh & 1)) {
            int n = hh >> 1;
            float* sp = g_states + (((long)n * BB + b) * HH + h) * (KK * KK);
#pragma unroll
            for (int r = 0; r < 4; r++) sp[(kq * 16 + sub * 4 + r) * KK + vd] = s[r];
        }
        if (hh + 1 < 2 * NCH) {
            WS_LOAD((hh + 1) & 1, hh + 1);
            asm volatile("cp.async.wait_group 1;" ::: "memory");
        } else {
            asm volatile("cp.async.wait_group 0;" ::: "memory");
        }
        __syncthreads();

        if (!(hh & 1)) {
#pragma unroll
            for (int r = 0; r < 4; r++) s[r] *= ws;
        }
        const float4* kk4 = (const float4*)(sms + (hh & 1) * 1024);
        const float* vv = sms + 2048 + (hh & 1) * 4096;
        const int jbase = (hh & 1) * 64;
#pragma unroll 4
        for (int j = 0; j < 64; j++) {
            float vj = vv[j * KK + vd] * wk_s[jbase + j];
            float4 k4 = kk4[j * 4 + sub];
            s[0] += k4.x * vj;
            s[1] += k4.y * vj;
            s[2] += k4.z * vj;
            s[3] += k4.w * vj;
        }
        __syncthreads();
    }
}

// ---------------- kernel 4: per-chunk output (128 thr) ----------------------
__global__ __launch_bounds__(128, 2) void wkv_out(const float* __restrict__ time_decay,
                                                  const float* __restrict__ time_faaaa) {
    extern __shared__ __align__(16) float sm[];
    float* ks = sm;
    float* vs = ks + TCH * KK;
    float* ss = vs + TCH * KK;
    __shared__ float pow_s[TCH];

    int id = blockIdx.x;
    int h = id % HH;
    int b = (id / HH) % BB;
    int n = id / (BB * HH);
    int tid = threadIdx.x;

    float et = expf(time_decay[h]);
    float u = time_faaaa[h];
    pow_s[tid] = expf(-et * (float)tid);

    long base = ((long)b * TTOT + (long)n * TCH) * CC + h * KK;
    const float* rg = g_r + base;
    const float* kg = g_k + base;
    const float* vg = g_v + base;

    for (int p = 0; p < 16; p++) {
        int j = p * 8 + tid / 16;
        int cc = (tid % 16) * 4;
        long off = (long)j * CC + cc;
        *(float4*)(ks + j * KK + cc) = *(const float4*)(kg + off);
        *(float4*)(vs + j * KK + cc) = *(const float4*)(vg + off);
    }
    {
        const float* sp = g_states + (((long)n * BB + b) * HH + h) * (KK * KK);
#pragma unroll
        for (int q = 0; q < 8; q++) {
            int idx = q * 512 + tid * 4;
            *(float4*)(ss + idx) = *(const float4*)(sp + idx);
        }
    }

    const int i = tid;
    float rr[64];
    {
        const float4* rrow = (const float4*)(rg + (long)i * CC);
#pragma unroll
        for (int q = 0; q < 16; q++) {
            float4 t = rrow[q];
            rr[4 * q + 0] = t.x;
            rr[4 * q + 1] = t.y;
            rr[4 * q + 2] = t.z;
            rr[4 * q + 3] = t.w;
        }
    }
    __syncthreads();

    float4 a4[16];
#pragma unroll
    for (int q = 0; q < 16; q++) a4[q] = make_float4(0.f, 0.f, 0.f, 0.f);

    const float4* ss4 = (const float4*)ss;
#pragma unroll 4
    for (int k = 0; k < 64; k++) {
        float rk = rr[k];
#pragma unroll
        for (int q = 0; q < 16; q++) {
            float4 s4 = ss4[k * 16 + q];
            a4[q].x += rk * s4.x;
            a4[q].y += rk * s4.y;
            a4[q].z += rk * s4.z;
            a4[q].w += rk * s4.w;
        }
    }
    float wbi = pow_s[i];
#pragma unroll
    for (int q = 0; q < 16; q++) {
        a4[q].x *= wbi; a4[q].y *= wbi; a4[q].z *= wbi; a4[q].w *= wbi;
    }

    const float4* ks4 = (const float4*)ks;
    const float4* vs4 = (const float4*)vs;
    for (int j = 0; j <= i; j++) {
        float a = 0.0f;
#pragma unroll
        for (int q = 0; q < 16; q++) {
            float4 k4 = ks4[j * 16 + q];
            a += rr[q * 4 + 0] * k4.x + rr[q * 4 + 1] * k4.y +
                 rr[q * 4 + 2] * k4.z + rr[q * 4 + 3] * k4.w;
        }
        float w = (j < i) ? pow_s[i - j - 1] : u;
        float aw = a * w;
#pragma unroll
        for (int q = 0; q < 16; q++) {
            float4 v4 = vs4[j * 16 + q];
            a4[q].x += aw * v4.x;
            a4[q].y += aw * v4.y;
            a4[q].z += aw * v4.z;
            a4[q].w += aw * v4.w;
        }
    }

    float4* xo4 = (float4*)(g_xo + base + (long)i * CC);
#pragma unroll
    for (int q = 0; q < 16; q++) xo4[q] = a4[q];
}

// ---------------- kernel 5: GroupNorm + SiLU gate -> fp16 -------------------
__global__ __launch_bounds__(256) void gn_gate(const float* __restrict__ ln_w,
                                               const float* __restrict__ ln_b) {
    int warp = threadIdx.x / 32;
    int lane = threadIdx.x % 32;
    long gid = (long)blockIdx.x * 8 + warp;
    int h = (int)(gid % HH);
    long bt = gid / HH;
    long base = bt * CC + h * 64;

    float y0 = g_xo[base + lane] * 0.125f;
    float y1 = g_xo[base + 32 + lane] * 0.125f;
    float s = y0 + y1;
#pragma unroll
    for (int o = 16; o > 0; o >>= 1) s += __shfl_xor_sync(0xffffffffu, s, o);
    float mean = s * (1.0f / 64.0f);
    float d0 = y0 - mean, d1 = y1 - mean;
    float v = d0 * d0 + d1 * d1;
#pragma unroll
    for (int o = 16; o > 0; o >>= 1) v += __shfl_xor_sync(0xffffffffu, v, o);
    float inv = rsqrtf(v * (1.0f / 64.0f) + 1e-5f);

    float w0 = ln_w[h * 64 + lane], b0 = ln_b[h * 64 + lane];
    float w1 = ln_w[h * 64 + 32 + lane], b1 = ln_b[h * 64 + 32 + lane];
    float o0 = d0 * inv * w0 + b0;
    float o1 = d1 * inv * w1 + b1;

    float gv0 = g_g[base + lane];
    float gv1 = g_g[base + 32 + lane];
    float s0 = gv0 / (1.0f + expf(-gv0));
    float s1 = gv1 / (1.0f + expf(-gv1));
    g_gh[base + lane] = __float2half(o0 * s0);
    g_gh[base + 32 + lane] = __float2half(o1 * s1);
}

// ---------------- launcher ----------------------------------------------------
extern "C" void kernel_launch(void* const* d_in, const int* in_sizes, int n_in,
                              void* d_out, int out_size) {
    const float* xq   = (const float*)d_in[0];
    const float* tmk  = (const float*)d_in[1];
    const float* tmv  = (const float*)d_in[2];
    const float* tmr  = (const float*)d_in[3];
    const float* tmg  = (const float*)d_in[4];
    const float* tdec = (const float*)d_in[5];
    const float* tfaa = (const float*)d_in[6];
    const float* W_r  = (const float*)d_in[7];
    const float* W_k  = (const float*)d_in[8];
    const float* W_v  = (const float*)d_in[9];
    const float* W_g  = (const float*)d_in[10];
    const float* W_o  = (const float*)d_in[11];
    const float* lnw  = (const float*)d_in[12];
    const float* lnb  = (const float*)d_in[13];
    float* out = (float*)d_out;

    __half *ah, *wh, *gh;
    float *pr, *pk, *pv, *pg;
    cudaGetSymbolAddress((void**)&ah, g_ah);
    cudaGetSymbolAddress((void**)&wh, g_wh);
    cudaGetSymbolAddress((void**)&gh, g_gh);
    cudaGetSymbolAddress((void**)&pr, g_r);
    cudaGetSymbolAddress((void**)&pk, g_k);
    cudaGetSymbolAddress((void**)&pv, g_v);
    cudaGetSymbolAddress((void**)&pg, g_g);

    static cudaStream_t s2 = nullptr;
    static cudaEvent_t e1 = nullptr, e2 = nullptr;
    if (s2 == nullptr) {
        cudaStreamCreateWithFlags(&s2, cudaStreamNonBlocking);
        cudaEventCreateWithFlags(&e1, cudaEventDisableTiming);
        cudaEventCreateWithFlags(&e2, cudaEventDisableTiming);
    }

    int smem_out = (2 * TCH * KK + KK * KK) * (int)sizeof(float);  // 81920
    cudaFuncSetAttribute(wkv_out, cudaFuncAttributeMaxDynamicSharedMemorySize, smem_out);
    cudaFuncSetAttribute(wkv_states, cudaFuncAttributeMaxDynamicSharedMemorySize, WS_SMEM);
    cudaFuncSetAttribute(gemm_fp16, cudaFuncAttributeMaxDynamicSharedMemorySize, G2_SMEM);

    // 0. weight fp16 conversion
    {
        WArgs wa;
        wa.w[0] = W_r; wa.w[1] = W_k; wa.w[2] = W_v; wa.w[3] = W_g; wa.w[4] = W_o;
        dim3 grid(WEL / 1024, 5);
        conv_w5<<<grid, 256>>>(wa);
    }

    // 1. token shift + mixes (fp16 only, no residuals)
    mix_kernel<<<ELEMS / 1024, 256>>>(xq, tmr, tmk, tmv, tmg);

    // 2. projection GEMMs for k, v, r (main, z=3, all single-product)
    {
        GArgs ga;
        // problem 0 = k, 1 = v, 2 = r
        ga.Ah[0] = ah + 1L * ELEMS; ga.Bh[0] = wh + 1L * WEL; ga.C[0] = pk;
        ga.Ah[1] = ah + 2L * ELEMS; ga.Bh[1] = wh + 2L * WEL; ga.C[1] = pv;
        ga.Ah[2] = ah;              ga.Bh[2] = wh;            ga.C[2] = pr;
        ga.Ah[3] = ga.Ah[0];        ga.Bh[3] = ga.Bh[0];      ga.C[3] = pk;
        for (int i = 0; i < 4; i++) { ga.Al[i] = ah; ga.useAl[i] = 0; }
        dim3 ggrid(CC / 128, MM / 128, 3);
        gemm_fp16<<<ggrid, 128, G2_SMEM>>>(ga);
    }

    // fork: s2 runs WKV while main runs GEMM g
    cudaEventRecord(e1, 0);
    cudaStreamWaitEvent(s2, e1, 0);

    wkv_states<<<BB * HH * 4, 256, WS_SMEM, s2>>>(tdec);
    wkv_out<<<NCH * BB * HH, 128, smem_out, s2>>>(tdec, tfaa);
    cudaEventRecord(e2, s2);

    // 2b. projection GEMM for g (single-product, main)
    {
        GArgs ga;
        for (int i = 0; i < 4; i++) {
            ga.Ah[i] = ah + 3L * ELEMS;
            ga.Al[i] = ah;
            ga.Bh[i] = wh + 3L * WEL;
            ga.C[i] = pg;
            ga.useAl[i] = 0;
        }
        dim3 ggrid(CC / 128, MM / 128, 1);
        gemm_fp16<<<ggrid, 128, G2_SMEM>>>(ga);
    }

    // join
    cudaStreamWaitEvent(0, e2, 0);

    // 5. GroupNorm + gate (fp16)
    gn_gate<<<(BB * TTOT * HH) / 8, 256>>>(lnw, lnb);

    // 6. output GEMM (single-product) -> d_out
    {
        GArgs ga;
        for (int i = 0; i < 4; i++) {
            ga.Ah[i] = gh;
            ga.Al[i] = gh;
            ga.Bh[i] = wh + 4L * WEL;
            ga.C[i] = out;
            ga.useAl[i] = 0;
        }
        dim3 ggrid(CC / 128, MM / 128, 1);
        gemm_fp16<<<ggrid, 128, G2_SMEM>>>(ga);
    }
}

// round 16
// speedup vs baseline: 1.5137x; 1.5137x over previous
#include <cuda_runtime.h>
#include <cuda_fp16.h>
#include <cstdint>

// Problem constants
#define BB 4
#define TTOT 4096
#define CC 1024
#define HH 16
#define KK 64
#define TCH 128
#define NCH 32            // TTOT / TCH
#define MM (BB * TTOT)    // 16384 rows
#define ELEMS (MM * CC)   // 16,777,216
#define WEL (CC * CC)

// ---------------- scratch (device globals; no allocation allowed) ----------
__device__ __half g_ah[4][ELEMS];   // mixes: r,k,v,g (fp16)
__device__ __half g_wh[5][WEL];     // weights fp16: r,k,v,g,o
__device__ float g_r[ELEMS];
__device__ float g_k[ELEMS];
__device__ float g_v[ELEMS];
__device__ float g_g[ELEMS];
__device__ float g_states[NCH * BB * HH * KK * KK];
__device__ float g_xo[ELEMS];
__device__ __half g_gh[ELEMS];      // gated output (fp16)

// ==================== mma.sync fp16 GEMM (1- or 2-product) ==================
// C = (Ah [+ Al]) @ Wh^T ; per-problem useAl flag (all 0 in this round).
// CTA 128x128, BK=32, 2-stage cp.async, 4 warps (2m x 2n), warp 64x64.
#define G2_PITCH 80
#define G2_TILE 10240                 // 128 rows * 80 B
#define G2_STAGE 30720                // Ah, Al, Bh
#define G2_SMEM 61440                 // 2 stages

struct GArgs {
    const __half* Ah[4];
    const __half* Al[4];
    const __half* Bh[4];
    float* C[4];
    int useAl[4];
};

#define CP16(dst, src) \
    asm volatile("cp.async.cg.shared.global [%0], [%1], 16;" :: "r"(dst), "l"(src) : "memory")

#define LDSM4(r0, r1, r2, r3, a) \
    asm volatile("ldmatrix.sync.aligned.m8n8.x4.shared.b16 {%0,%1,%2,%3}, [%4];" \
                 : "=r"(r0), "=r"(r1), "=r"(r2), "=r"(r3) : "r"(a))

#define MMA16816(d, a, b0, b1) \
    asm volatile("mma.sync.aligned.m16n8k16.row.col.f32.f16.f16.f32 " \
                 "{%0,%1,%2,%3},{%4,%5,%6,%7},{%8,%9},{%0,%1,%2,%3};" \
                 : "+f"((d)[0]), "+f"((d)[1]), "+f"((d)[2]), "+f"((d)[3]) \
                 : "r"((a)[0]), "r"((a)[1]), "r"((a)[2]), "r"((a)[3]), "r"(b0), "r"(b1))

__global__ __launch_bounds__(128, 2) void gemm_fp16(GArgs ga) {
    extern __shared__ __align__(128) char smraw[];
    const uint32_t smb = (uint32_t)__cvta_generic_to_shared(smraw);
    const int prob = blockIdx.z;
    const __half* __restrict__ Ahi = ga.Ah[prob];
    const __half* __restrict__ Alo = ga.Al[prob];
    const __half* __restrict__ Bhi = ga.Bh[prob];
    float* __restrict__ C = ga.C[prob];
    const bool useAl = ga.useAl[prob] != 0;

    const int tid = threadIdx.x;
    const int lane = tid & 31;
    const int wid = tid >> 5;
    const int warp_m = wid & 1;
    const int warp_n = wid >> 1;
    const int m0 = blockIdx.y * 128;
    const int n0 = blockIdx.x * 128;

    const int lrow = tid >> 2;        // 0..31
    const int lseg = tid & 3;
    const long arow0 = (long)(m0 + lrow) * CC + lseg * 8;
    const long brow0 = (long)(n0 + lrow) * CC + lseg * 8;
    const uint32_t dof0 = lrow * G2_PITCH + lseg * 16;

#define G2_LOAD(s, ch) do {                                                  \
        uint32_t st_ = smb + (s) * G2_STAGE;                                 \
        long kb_ = (long)(ch) * 32;                                          \
        _Pragma("unroll")                                                    \
        for (int i_ = 0; i_ < 4; i_++) {                                     \
            long ro_ = (long)i_ * 32 * CC + kb_;                             \
            uint32_t do_ = dof0 + i_ * 32 * G2_PITCH;                        \
            CP16(st_ + do_,               Ahi + arow0 + ro_);                \
            if (useAl) CP16(st_ + G2_TILE + do_, Alo + arow0 + ro_);         \
            CP16(st_ + 2 * G2_TILE + do_, Bhi + brow0 + ro_);                \
        }                                                                    \
        asm volatile("cp.async.commit_group;" ::: "memory");                 \
    } while (0)

    float acc[4][8][4];
#pragma unroll
    for (int mt = 0; mt < 4; mt++)
#pragma unroll
        for (int j = 0; j < 8; j++)
#pragma unroll
            for (int q = 0; q < 4; q++) acc[mt][j][q] = 0.0f;

    const int g = lane >> 3;
    const uint32_t aoff = (uint32_t)((warp_m * 64 + ((g & 1) << 3) + (lane & 7)) * G2_PITCH
                                     + ((g >> 1) << 4));
    const uint32_t boff = (uint32_t)((warp_n * 64 + ((g >> 1) << 3) + (lane & 7)) * G2_PITCH
                                     + ((g & 1) << 4));

    G2_LOAD(0, 0);

    for (int c = 0; c < 32; ++c) {
        if (c + 1 < 32) G2_LOAD((c + 1) & 1, c + 1);
        if (c + 1 < 32)
            asm volatile("cp.async.wait_group 1;" ::: "memory");
        else
            asm volatile("cp.async.wait_group 0;" ::: "memory");
        __syncthreads();

        uint32_t st = smb + (c & 1) * G2_STAGE;
#pragma unroll
        for (int ks = 0; ks < 2; ks++) {
            uint32_t ko = ks * 32;
            uint32_t ah_[4][4];
#pragma unroll
            for (int mt = 0; mt < 4; mt++)
                LDSM4(ah_[mt][0], ah_[mt][1], ah_[mt][2], ah_[mt][3],
                      st + aoff + mt * (16 * G2_PITCH) + ko);
            uint32_t bh_[8][2];
#pragma unroll
            for (int t = 0; t < 4; t++)
                LDSM4(bh_[2 * t][0], bh_[2 * t][1], bh_[2 * t + 1][0], bh_[2 * t + 1][1],
                      st + 2 * G2_TILE + boff + t * (16 * G2_PITCH) + ko);
            // P1: Ah x Bh
#pragma unroll
            for (int mt = 0; mt < 4; mt++)
#pragma unroll
                for (int j = 0; j < 8; j++)
                    MMA16816(acc[mt][j], ah_[mt], bh_[j][0], bh_[j][1]);
            // P2: Al x Bh (disabled this round)
            if (useAl) {
                uint32_t al_[4][4];
#pragma unroll
                for (int mt = 0; mt < 4; mt++)
                    LDSM4(al_[mt][0], al_[mt][1], al_[mt][2], al_[mt][3],
                          st + G2_TILE + aoff + mt * (16 * G2_PITCH) + ko);
#pragma unroll
                for (int mt = 0; mt < 4; mt++)
#pragma unroll
                    for (int j = 0; j < 8; j++)
                        MMA16816(acc[mt][j], al_[mt], bh_[j][0], bh_[j][1]);
            }
        }
        __syncthreads();
    }

    const int erow = m0 + warp_m * 64 + (lane >> 2);
    const int ecol = n0 + warp_n * 64 + (lane & 3) * 2;
#pragma unroll
    for (int mt = 0; mt < 4; mt++) {
#pragma unroll
        for (int j = 0; j < 8; j++) {
            long r = erow + mt * 16;
            int cc2 = ecol + j * 8;
            *(float2*)(C + r * CC + cc2) = make_float2(acc[mt][j][0], acc[mt][j][1]);
            *(float2*)(C + (r + 8) * CC + cc2) = make_float2(acc[mt][j][2], acc[mt][j][3]);
        }
    }
}

// ---------------- weight fp32 -> fp16 (all 5, vectorized) -------------------
struct WArgs { const float* w[5]; };

__global__ __launch_bounds__(256) void conv_w5(WArgs wa) {
    const int wi = blockIdx.y;
    const float* __restrict__ src = wa.w[wi];
    long e0 = ((long)blockIdx.x * 256 + threadIdx.x) * 4;
    float4 x4 = *(const float4*)(src + e0);
    __half2* hp = (__half2*)&g_wh[wi][e0];
    hp[0] = __floats2half2_rn(x4.x, x4.y);
    hp[1] = __floats2half2_rn(x4.z, x4.w);
}

// ---------------- kernel 1: token shift + 4 mixes -> fp16 -------------------
__global__ __launch_bounds__(256) void mix_kernel(const float* __restrict__ x,
                                                  const float* __restrict__ tmr,
                                                  const float* __restrict__ tmk,
                                                  const float* __restrict__ tmv,
                                                  const float* __restrict__ tmg) {
    long e0 = ((long)blockIdx.x * 256 + threadIdx.x) * 4;
    if (e0 >= (long)ELEMS) return;
    int c = (int)(e0 % CC);
    long row = e0 / CC;
    int t = (int)(row % TTOT);
    float4 xv = *(const float4*)(x + e0);
    float4 xx = (t > 0) ? *(const float4*)(x + e0 - CC) : make_float4(0.f, 0.f, 0.f, 0.f);
    const float* tms[4] = {tmr, tmk, tmv, tmg};
#pragma unroll
    for (int mi = 0; mi < 4; mi++) {
        float4 m = *(const float4*)(tms[mi] + c);
        float y0 = xv.x * m.x + xx.x * (1.0f - m.x);
        float y1 = xv.y * m.y + xx.y * (1.0f - m.y);
        float y2 = xv.z * m.z + xx.z * (1.0f - m.z);
        float y3 = xv.w * m.w + xx.w * (1.0f - m.w);
        __half2* hp = (__half2*)&g_ah[mi][e0];
        hp[0] = __floats2half2_rn(y0, y1);
        hp[1] = __floats2half2_rn(y2, y3);
    }
}

// ---------------- kernel 3: state sweep, half-chunk staging (40 KB smem) ----
#define WS_SMEM 40960
__global__ __launch_bounds__(256) void wkv_states(const float* __restrict__ time_decay) {
    extern __shared__ __align__(16) float sms[];
    const uint32_t smb = (uint32_t)__cvta_generic_to_shared(sms);
    __shared__ float wk_s[TCH];

    int bx = blockIdx.x;             // 0..255
    int bh = bx >> 2, kq = bx & 3;
    int b = bh / HH, h = bh % HH;
    int tid = threadIdx.x;
    int vd = tid & 63, sub = tid >> 6;
    float et = expf(time_decay[h]);
    float ws = expf(-et * (float)TCH);

    const float* kg = g_k + ((long)b * TTOT) * CC + h * KK + kq * 16;
    const float* vg = g_v + ((long)b * TTOT) * CC + h * KK;

#define WS_LOAD(buf, hh) do {                                                    \
        uint32_t kdst = smb + (buf) * 4096;                                      \
        uint32_t vdst = smb + 8192 + (buf) * 16384;                              \
        {                                                                        \
            int row_ = tid >> 2, c4_ = tid & 3;                                  \
            CP16(kdst + row_ * 64 + c4_ * 16,                                    \
                 kg + (long)((hh) * 64 + row_) * CC + c4_ * 4);                  \
        }                                                                        \
        _Pragma("unroll")                                                        \
        for (int it_ = 0; it_ < 4; it_++) {                                      \
            int f_ = it_ * 256 + tid, row_ = f_ >> 4, c4_ = f_ & 15;             \
            CP16(vdst + row_ * 256 + c4_ * 16,                                   \
                 vg + (long)((hh) * 64 + row_) * CC + c4_ * 4);                  \
        }                                                                        \
        asm volatile("cp.async.commit_group;" ::: "memory");                     \
    } while (0)

    WS_LOAD(0, 0);
    if (tid < TCH) wk_s[tid] = expf(-et * (float)(TCH - 1 - tid));

    float s[4] = {0.f, 0.f, 0.f, 0.f};

    for (int hh = 0; hh < 2 * NCH; hh++) {
        if (!(hh & 1)) {
            int n = hh >> 1;
            float* sp = g_states + (((long)n * BB + b) * HH + h) * (KK * KK);
#pragma unroll
            for (int r = 0; r < 4; r++) sp[(kq * 16 + sub * 4 + r) * KK + vd] = s[r];
        }
        if (hh + 1 < 2 * NCH) {
            WS_LOAD((hh + 1) & 1, hh + 1);
            asm volatile("cp.async.wait_group 1;" ::: "memory");
        } else {
            asm volatile("cp.async.wait_group 0;" ::: "memory");
        }
        __syncthreads();

        if (!(hh & 1)) {
#pragma unroll
            for (int r = 0; r < 4; r++) s[r] *= ws;
        }
        const float4* kk4 = (const float4*)(sms + (hh & 1) * 1024);
        const float* vv = sms + 2048 + (hh & 1) * 4096;
        const int jbase = (hh & 1) * 64;
#pragma unroll 4
        for (int j = 0; j < 64; j++) {
            float vj = vv[j * KK + vd] * wk_s[jbase + j];
            float4 k4 = kk4[j * 4 + sub];
            s[0] += k4.x * vj;
            s[1] += k4.y * vj;
            s[2] += k4.z * vj;
            s[3] += k4.w * vj;
        }
        __syncthreads();
    }
}

// ---------------- kernel 4: per-chunk output (128 thr) ----------------------
__global__ __launch_bounds__(128, 2) void wkv_out(const float* __restrict__ time_decay,
                                                  const float* __restrict__ time_faaaa) {
    extern __shared__ __align__(16) float sm[];
    float* ks = sm;
    float* vs = ks + TCH * KK;
    float* ss = vs + TCH * KK;
    __shared__ float pow_s[TCH];

    int id = blockIdx.x;
    int h = id % HH;
    int b = (id / HH) % BB;
    int n = id / (BB * HH);
    int tid = threadIdx.x;

    float et = expf(time_decay[h]);
    float u = time_faaaa[h];
    pow_s[tid] = expf(-et * (float)tid);

    long base = ((long)b * TTOT + (long)n * TCH) * CC + h * KK;
    const float* rg = g_r + base;
    const float* kg = g_k + base;
    const float* vg = g_v + base;

    for (int p = 0; p < 16; p++) {
        int j = p * 8 + tid / 16;
        int cc = (tid % 16) * 4;
        long off = (long)j * CC + cc;
        *(float4*)(ks + j * KK + cc) = *(const float4*)(kg + off);
        *(float4*)(vs + j * KK + cc) = *(const float4*)(vg + off);
    }
    {
        const float* sp = g_states + (((long)n * BB + b) * HH + h) * (KK * KK);
#pragma unroll
        for (int q = 0; q < 8; q++) {
            int idx = q * 512 + tid * 4;
            *(float4*)(ss + idx) = *(const float4*)(sp + idx);
        }
    }

    const int i = tid;
    float rr[64];
    {
        const float4* rrow = (const float4*)(rg + (long)i * CC);
#pragma unroll
        for (int q = 0; q < 16; q++) {
            float4 t = rrow[q];
            rr[4 * q + 0] = t.x;
            rr[4 * q + 1] = t.y;
            rr[4 * q + 2] = t.z;
            rr[4 * q + 3] = t.w;
        }
    }
    __syncthreads();

    float4 a4[16];
#pragma unroll
    for (int q = 0; q < 16; q++) a4[q] = make_float4(0.f, 0.f, 0.f, 0.f);

    const float4* ss4 = (const float4*)ss;
#pragma unroll 4
    for (int k = 0; k < 64; k++) {
        float rk = rr[k];
#pragma unroll
        for (int q = 0; q < 16; q++) {
            float4 s4 = ss4[k * 16 + q];
            a4[q].x += rk * s4.x;
            a4[q].y += rk * s4.y;
            a4[q].z += rk * s4.z;
            a4[q].w += rk * s4.w;
        }
    }
    float wbi = pow_s[i];
#pragma unroll
    for (int q = 0; q < 16; q++) {
        a4[q].x *= wbi; a4[q].y *= wbi; a4[q].z *= wbi; a4[q].w *= wbi;
    }

    const float4* ks4 = (const float4*)ks;
    const float4* vs4 = (const float4*)vs;
    for (int j = 0; j <= i; j++) {
        float a = 0.0f;
#pragma unroll
        for (int q = 0; q < 16; q++) {
            float4 k4 = ks4[j * 16 + q];
            a += rr[q * 4 + 0] * k4.x + rr[q * 4 + 1] * k4.y +
                 rr[q * 4 + 2] * k4.z + rr[q * 4 + 3] * k4.w;
        }
        float w = (j < i) ? pow_s[i - j - 1] : u;
        float aw = a * w;
#pragma unroll
        for (int q = 0; q < 16; q++) {
            float4 v4 = vs4[j * 16 + q];
            a4[q].x += aw * v4.x;
            a4[q].y += aw * v4.y;
            a4[q].z += aw * v4.z;
            a4[q].w += aw * v4.w;
        }
    }

    float4* xo4 = (float4*)(g_xo + base + (long)i * CC);
#pragma unroll
    for (int q = 0; q < 16; q++) xo4[q] = a4[q];
}

// ---------------- kernel 5: GroupNorm + SiLU gate -> fp16 -------------------
__global__ __launch_bounds__(256) void gn_gate(const float* __restrict__ ln_w,
                                               const float* __restrict__ ln_b) {
    int warp = threadIdx.x / 32;
    int lane = threadIdx.x % 32;
    long gid = (long)blockIdx.x * 8 + warp;
    int h = (int)(gid % HH);
    long bt = gid / HH;
    long base = bt * CC + h * 64;

    float y0 = g_xo[base + lane] * 0.125f;
    float y1 = g_xo[base + 32 + lane] * 0.125f;
    float s = y0 + y1;
#pragma unroll
    for (int o = 16; o > 0; o >>= 1) s += __shfl_xor_sync(0xffffffffu, s, o);
    float mean = s * (1.0f / 64.0f);
    float d0 = y0 - mean, d1 = y1 - mean;
    float v = d0 * d0 + d1 * d1;
#pragma unroll
    for (int o = 16; o > 0; o >>= 1) v += __shfl_xor_sync(0xffffffffu, v, o);
    float inv = rsqrtf(v * (1.0f / 64.0f) + 1e-5f);

    float w0 = ln_w[h * 64 + lane], b0 = ln_b[h * 64 + lane];
    float w1 = ln_w[h * 64 + 32 + lane], b1 = ln_b[h * 64 + 32 + lane];
    float o0 = d0 * inv * w0 + b0;
    float o1 = d1 * inv * w1 + b1;

    float gv0 = g_g[base + lane];
    float gv1 = g_g[base + 32 + lane];
    float s0 = gv0 / (1.0f + expf(-gv0));
    float s1 = gv1 / (1.0f + expf(-gv1));
    g_gh[base + lane] = __float2half(o0 * s0);
    g_gh[base + 32 + lane] = __float2half(o1 * s1);
}

// ---------------- launcher ----------------------------------------------------
extern "C" void kernel_launch(void* const* d_in, const int* in_sizes, int n_in,
                              void* d_out, int out_size) {
    const float* xq   = (const float*)d_in[0];
    const float* tmk  = (const float*)d_in[1];
    const float* tmv  = (const float*)d_in[2];
    const float* tmr  = (const float*)d_in[3];
    const float* tmg  = (const float*)d_in[4];
    const float* tdec = (const float*)d_in[5];
    const float* tfaa = (const float*)d_in[6];
    const float* W_r  = (const float*)d_in[7];
    const float* W_k  = (const float*)d_in[8];
    const float* W_v  = (const float*)d_in[9];
    const float* W_g  = (const float*)d_in[10];
    const float* W_o  = (const float*)d_in[11];
    const float* lnw  = (const float*)d_in[12];
    const float* lnb  = (const float*)d_in[13];
    float* out = (float*)d_out;

    __half *ah, *wh, *gh;
    float *pr, *pk, *pv, *pg;
    cudaGetSymbolAddress((void**)&ah, g_ah);
    cudaGetSymbolAddress((void**)&wh, g_wh);
    cudaGetSymbolAddress((void**)&gh, g_gh);
    cudaGetSymbolAddress((void**)&pr, g_r);
    cudaGetSymbolAddress((void**)&pk, g_k);
    cudaGetSymbolAddress((void**)&pv, g_v);
    cudaGetSymbolAddress((void**)&pg, g_g);

    static cudaStream_t s2 = nullptr;
    static cudaEvent_t e1 = nullptr, e2 = nullptr;
    if (s2 == nullptr) {
        cudaStreamCreateWithFlags(&s2, cudaStreamNonBlocking);
        cudaEventCreateWithFlags(&e1, cudaEventDisableTiming);
        cudaEventCreateWithFlags(&e2, cudaEventDisableTiming);
    }

    int smem_out = (2 * TCH * KK + KK * KK) * (int)sizeof(float);  // 81920
    cudaFuncSetAttribute(wkv_out, cudaFuncAttributeMaxDynamicSharedMemorySize, smem_out);
    cudaFuncSetAttribute(wkv_states, cudaFuncAttributeMaxDynamicSharedMemorySize, WS_SMEM);
    cudaFuncSetAttribute(gemm_fp16, cudaFuncAttributeMaxDynamicSharedMemorySize, G2_SMEM);

    // 0. weight fp16 conversion
    {
        WArgs wa;
        wa.w[0] = W_r; wa.w[1] = W_k; wa.w[2] = W_v; wa.w[3] = W_g; wa.w[4] = W_o;
        dim3 grid(WEL / 1024, 5);
        conv_w5<<<grid, 256>>>(wa);
    }

    // 1. token shift + mixes (fp16 only, no residuals)
    mix_kernel<<<ELEMS / 1024, 256>>>(xq, tmr, tmk, tmv, tmg);

    // 2. projection GEMMs for k, v, r (main, z=3, all single-product)
    {
        GArgs ga;
        // problem 0 = k, 1 = v, 2 = r
        ga.Ah[0] = ah + 1L * ELEMS; ga.Bh[0] = wh + 1L * WEL; ga.C[0] = pk;
        ga.Ah[1] = ah + 2L * ELEMS; ga.Bh[1] = wh + 2L * WEL; ga.C[1] = pv;
        ga.Ah[2] = ah;              ga.Bh[2] = wh;            ga.C[2] = pr;
        ga.Ah[3] = ga.Ah[0];        ga.Bh[3] = ga.Bh[0];      ga.C[3] = pk;
        for (int i = 0; i < 4; i++) { ga.Al[i] = ah; ga.useAl[i] = 0; }
        dim3 ggrid(CC / 128, MM / 128, 3);
        gemm_fp16<<<ggrid, 128, G2_SMEM>>>(ga);
    }

    // fork: s2 runs WKV while main runs GEMM g
    cudaEventRecord(e1, 0);
    cudaStreamWaitEvent(s2, e1, 0);

    wkv_states<<<BB * HH * 4, 256, WS_SMEM, s2>>>(tdec);
    wkv_out<<<NCH * BB * HH, 128, smem_out, s2>>>(tdec, tfaa);
    cudaEventRecord(e2, s2);

    // 2b. projection GEMM for g (single-product, main)
    {
        GArgs ga;
        for (int i = 0; i < 4; i++) {
            ga.Ah[i] = ah + 3L * ELEMS;
            ga.Al[i] = ah;
            ga.Bh[i] = wh + 3L * WEL;
            ga.C[i] = pg;
            ga.useAl[i] = 0;
        }
        dim3 ggrid(CC / 128, MM / 128, 1);
        gemm_fp16<<<ggrid, 128, G2_SMEM>>>(ga);
    }

    // join
    cudaStreamWaitEvent(0, e2, 0);

    // 5. GroupNorm + gate (fp16)
    gn_gate<<<(BB * TTOT * HH) / 8, 256>>>(lnw, lnb);

    // 6. output GEMM (single-product) -> d_out
    {
        GArgs ga;
        for (int i = 0; i < 4; i++) {
            ga.Ah[i] = gh;
            ga.Al[i] = gh;
            ga.Bh[i] = wh + 4L * WEL;
            ga.C[i] = out;
            ga.useAl[i] = 0;
        }
        dim3 ggrid(CC / 128, MM / 128, 1);
        gemm_fp16<<<ggrid, 128, G2_SMEM>>>(ga);
    }
}